// round 16
// baseline (speedup 1.0000x reference)
#include <cuda_runtime.h>
#include <cuda_fp16.h>
#include <math.h>
#include <stdint.h>

#define MD 1024      // model size D
#define NH 16        // heads
#define HD 64        // head dim
#define NB 8         // batch
#define NS 1024      // seq len
#define MROWS (NB*NS)   // 8192

// ---------------- scratch (static device globals; no allocation allowed) ---
__device__ __half g_xq[MROWS * MD];        // 16 MB fp16 query
__device__ __half g_xv[MROWS * MD];        // 16 MB fp16 value
__device__ __half g_q16[MROWS * MD];       // 16 MB
__device__ __half g_kv16[MROWS * 2 * MD];  // 32 MB
__device__ __half g_h16[MROWS * MD];       // 16 MB
__device__ __half g_wt16[4 * MD * MD];     // 8 MB: [0]=WqT, [1,2]=WkvT, [3]=WoT

// ======================== PTX helpers ======================================
static __device__ __forceinline__ void cp_async16(void* dst_smem, const void* src_gmem) {
    unsigned s = (unsigned)__cvta_generic_to_shared(dst_smem);
    asm volatile("cp.async.cg.shared.global [%0], [%1], 16;" :: "r"(s), "l"(src_gmem));
}
#define CP_COMMIT()  asm volatile("cp.async.commit_group;" ::: "memory")
#define CP_WAIT(n)   asm volatile("cp.async.wait_group %0;" :: "n"(n) : "memory")

static __device__ __forceinline__ void ldsm4(uint32_t* r, uint32_t addr) {
    asm volatile("ldmatrix.sync.aligned.m8n8.x4.shared.b16 {%0,%1,%2,%3}, [%4];"
        : "=r"(r[0]), "=r"(r[1]), "=r"(r[2]), "=r"(r[3]) : "r"(addr));
}
static __device__ __forceinline__ void ldsm4t(uint32_t* r, uint32_t addr) {
    asm volatile("ldmatrix.sync.aligned.m8n8.x4.trans.shared.b16 {%0,%1,%2,%3}, [%4];"
        : "=r"(r[0]), "=r"(r[1]), "=r"(r[2]), "=r"(r[3]) : "r"(addr));
}
static __device__ __forceinline__ void mma16(float* c, const uint32_t* a,
                                             uint32_t b0, uint32_t b1) {
    asm volatile("mma.sync.aligned.m16n8k16.row.col.f32.f16.f16.f32 "
        "{%0,%1,%2,%3}, {%4,%5,%6,%7}, {%8,%9}, {%0,%1,%2,%3};"
        : "+f"(c[0]), "+f"(c[1]), "+f"(c[2]), "+f"(c[3])
        : "r"(a[0]), "r"(a[1]), "r"(a[2]), "r"(a[3]), "r"(b0), "r"(b1));
}
// 128-byte-row XOR swizzle: byte bits [4:6] ^= bits [7:9]
#define SWZ(o) ((o) ^ ((((uint32_t)(o)) >> 3) & 0x70u))

// ---------------------------------------------------------------------------
// fp32 -> fp16 convert, BOTH inputs in one launch (float4 grid-stride)
// ---------------------------------------------------------------------------
__global__ void f2h_both(const float* __restrict__ x0, __half* __restrict__ y0,
                         const float* __restrict__ x1, __half* __restrict__ y1,
                         int n4)
{
    int i = blockIdx.x * blockDim.x + threadIdx.x;
    const int stride = gridDim.x * blockDim.x;
    for (; i < n4; i += stride) {
        const float4 v = ((const float4*)x0)[i];
        __half2 h0 = __floats2half2_rn(v.x, v.y);
        __half2 h1 = __floats2half2_rn(v.z, v.w);
        uint2 u;
        u.x = *(uint32_t*)&h0; u.y = *(uint32_t*)&h1;
        ((uint2*)y0)[i] = u;
        const float4 w = ((const float4*)x1)[i];
        h0 = __floats2half2_rn(w.x, w.y);
        h1 = __floats2half2_rn(w.z, w.w);
        u.x = *(uint32_t*)&h0; u.y = *(uint32_t*)&h1;
        ((uint2*)y1)[i] = u;
    }
}

// ---------------------------------------------------------------------------
// Weight transpose + fp16 round: Wt[n][k] = fp16(W[k][n]).
// ---------------------------------------------------------------------------
__global__ void transpose_h(const float* __restrict__ W, __half* __restrict__ Wt,
                            int K, int N)
{
    __shared__ float t[32][33];
    const int n0 = blockIdx.x * 32, k0 = blockIdx.y * 32;
    const int tx = threadIdx.x, ty = threadIdx.y;
#pragma unroll
    for (int j = 0; j < 32; j += 8)
        t[ty + j][tx] = W[(size_t)(k0 + ty + j) * N + n0 + tx];
    __syncthreads();
#pragma unroll
    for (int j = 0; j < 32; j += 8)
        Wt[(size_t)(n0 + ty + j) * K + k0 + tx] = __float2half_rn(t[tx][ty + j]);
}

// ===========================================================================
// Shared GEMM core: CTA 128x128, BK=64, 8 warps (2x4) of 64x32 tiles,
// 3-stage cp.async pipeline, one __syncthreads per k-tile. K = MD = 1024.
// ===========================================================================
#define GEMM_SMEM 98304

struct GemmCore {
    const __half* Ab;    // A block base  [128 rows x K]
    const __half* Bb;    // Bt block base [128 rows x K]
    float c[4][4][4];
    uint32_t sbase, xorv, kA, kB;
    uint32_t aRow[4], bRow[2];
    int lane, warpM, warpN;

    __device__ __forceinline__ void init(const char* smem, int tid) {
        lane = tid & 31;
        const int wid = tid >> 5;
        warpM = wid >> 2;
        warpN = wid & 3;
#pragma unroll
        for (int i = 0; i < 4; i++)
#pragma unroll
            for (int j = 0; j < 4; j++)
#pragma unroll
                for (int e = 0; e < 4; e++) c[i][j][e] = 0.0f;
        sbase = (uint32_t)__cvta_generic_to_shared(smem);
        const int l7 = lane & 7;
        xorv = (uint32_t)l7 * 16u;
        const int rA = l7 + ((lane >> 3) & 1) * 8;
        kA = ((lane >> 4) & 1) * 16;
#pragma unroll
        for (int i = 0; i < 4; i++)
            aRow[i] = (uint32_t)(warpM * 64 + i * 16 + rA) * 128u;
        const int rB = l7 + ((lane >> 4) & 1) * 8;
        kB = ((lane >> 3) & 1) * 16;
#pragma unroll
        for (int j = 0; j < 2; j++)
            bRow[j] = (uint32_t)(warpN * 32 + j * 16 + rB) * 128u;
    }

    __device__ __forceinline__ void load_tile(char* smem, int tid, int t, int buf) {
        const int k0 = t * 64;
        char* sA = smem + buf * 32768;
        char* sB = sA + 16384;
#pragma unroll
        for (int i = 0; i < 4; i++) {
            const int idx = tid + i * 256;
            const int row = idx >> 3, ch = idx & 7;
            const uint32_t off = SWZ((uint32_t)(row * 128 + ch * 16));
            cp_async16(sA + off, Ab + (size_t)row * MD + k0 + ch * 8);
            cp_async16(sB + off, Bb + (size_t)row * MD + k0 + ch * 8);
        }
    }

    __device__ __forceinline__ void run(char* smem, int tid) {
        load_tile(smem, tid, 0, 0); CP_COMMIT();
        load_tile(smem, tid, 1, 1); CP_COMMIT();
        const int NT = MD / 64;   // 16
        int buf = 0;
        for (int t = 0; t < NT; t++) {
            if (t < NT - 1) { CP_WAIT(1); } else { CP_WAIT(0); }
            __syncthreads();
            if (t + 2 < NT) {
                int nb = buf + 2; if (nb >= 3) nb -= 3;
                load_tile(smem, tid, t + 2, nb);
                CP_COMMIT();
            }
            const uint32_t aBase = sbase + buf * 32768;
            const uint32_t bBase = aBase + 16384;
#pragma unroll
            for (int slab = 0; slab < 4; slab++) {
                const uint32_t so = (uint32_t)slab * 32u;
                uint32_t a[4][4], b[2][4];
#pragma unroll
                for (int i = 0; i < 4; i++)
                    ldsm4(a[i], aBase + aRow[i] + ((so + kA) ^ xorv));
#pragma unroll
                for (int j = 0; j < 2; j++)
                    ldsm4(b[j], bBase + bRow[j] + ((so + kB) ^ xorv));
#pragma unroll
                for (int mi = 0; mi < 4; mi++)
#pragma unroll
                    for (int nj = 0; nj < 4; nj++)
                        mma16(c[mi][nj], a[mi],
                              b[nj >> 1][(nj & 1) * 2], b[nj >> 1][(nj & 1) * 2 + 1]);
            }
            if (++buf == 3) buf = 0;
        }
    }
};

// ---------------------------------------------------------------------------
// Merged Q+KV projection: grid.x 0..7 -> q tile cols, 8..23 -> kv tile cols.
// ---------------------------------------------------------------------------
__global__ __launch_bounds__(256)
void gemm_proj(const __half* __restrict__ xq, const __half* __restrict__ xv,
               const __half* __restrict__ wt,   // [0]=WqT, [MD*MD]=WkvT
               const float* __restrict__ bq, const float* __restrict__ bkv,
               __half* __restrict__ q16, __half* __restrict__ kv16)
{
    extern __shared__ char smem[];
    const int tid = threadIdx.x;
    const int bnr = blockIdx.x, bm = blockIdx.y;

    const __half* A;
    const __half* Bt;
    const float* bias;
    __half* C;
    int N, bn;
    if (bnr < 8) {
        A = xq;  Bt = wt;            bias = bq;  C = q16;  N = MD;      bn = bnr;
    } else {
        A = xv;  Bt = wt + MD * MD;  bias = bkv; C = kv16; N = 2 * MD;  bn = bnr - 8;
    }

    GemmCore g;
    g.init(smem, tid);
    g.Ab = A  + (size_t)bm * 128 * MD;
    g.Bb = Bt + (size_t)bn * 128 * MD;
    g.run(smem, tid);

    // epilogue: fp16 out + bias
#pragma unroll
    for (int mi = 0; mi < 4; mi++) {
        const int row0 = bm * 128 + g.warpM * 64 + mi * 16 + (g.lane >> 2);
#pragma unroll
        for (int nj = 0; nj < 4; nj++) {
            const int col = bn * 128 + g.warpN * 32 + nj * 8 + (g.lane & 3) * 2;
            const float2 bv = *(const float2*)(bias + col);
            __half2 h0 = __floats2half2_rn(g.c[mi][nj][0] + bv.x, g.c[mi][nj][1] + bv.y);
            __half2 h1 = __floats2half2_rn(g.c[mi][nj][2] + bv.x, g.c[mi][nj][3] + bv.y);
            *(__half2*)(C + (size_t)row0 * N + col) = h0;
            *(__half2*)(C + (size_t)(row0 + 8) * N + col) = h1;
        }
    }
}

// ---------------------------------------------------------------------------
// O projection: fp16 in, fp32 out.
// ---------------------------------------------------------------------------
__global__ __launch_bounds__(256)
void gemm_out(const __half* __restrict__ A, const __half* __restrict__ Bt,
              const float* __restrict__ bias, float* __restrict__ C)
{
    extern __shared__ char smem[];
    const int tid = threadIdx.x;
    const int bn = blockIdx.x, bm = blockIdx.y;

    GemmCore g;
    g.init(smem, tid);
    g.Ab = A  + (size_t)bm * 128 * MD;
    g.Bb = Bt + (size_t)bn * 128 * MD;
    g.run(smem, tid);

#pragma unroll
    for (int mi = 0; mi < 4; mi++) {
        const int row0 = bm * 128 + g.warpM * 64 + mi * 16 + (g.lane >> 2);
#pragma unroll
        for (int nj = 0; nj < 4; nj++) {
            const int col = bn * 128 + g.warpN * 32 + nj * 8 + (g.lane & 3) * 2;
            const float2 bv = *(const float2*)(bias + col);
            *(float2*)(C + (size_t)row0 * MD + col) =
                make_float2(g.c[mi][nj][0] + bv.x, g.c[mi][nj][1] + bv.y);
            *(float2*)(C + (size_t)(row0 + 8) * MD + col) =
                make_float2(g.c[mi][nj][2] + bv.x, g.c[mi][nj][3] + bv.y);
        }
    }
}

// ---------------------------------------------------------------------------
// fp16 tensor-core flash attention, 3-stage K/V pipeline, 1 sync per tile.
// (identical to round 13)
// ---------------------------------------------------------------------------
#define ATTN_SMEM 81920
#define QOFF 0
#define POFF 16384
#define KVOFF 32768

__global__ __launch_bounds__(256, 2)
void attn_h(const __half* __restrict__ q, const __half* __restrict__ kv,
            __half* __restrict__ heads)
{
    extern __shared__ char smc[];
    const uint32_t sb = (uint32_t)__cvta_generic_to_shared(smc);

    const int b = blockIdx.z, h = blockIdx.y, qt = blockIdx.x;
    const int tid = threadIdx.x, lane = tid & 31, w = tid >> 5;
    const float scale = 0.125f;   // 1/sqrt(64)

    const int l7 = lane & 7;
    const uint32_t xorv = (uint32_t)l7 * 16u;
    const int rA = l7 + ((lane >> 3) & 1) * 8;
    const uint32_t kA = ((lane >> 4) & 1) * 16;
    const uint32_t aRowOff = (uint32_t)(w * 16 + rA) * 128u;

    const int rB = l7 + ((lane >> 4) & 1) * 8;
    const uint32_t kB = ((lane >> 3) & 1) * 16;
    uint32_t bRow[4];
#pragma unroll
    for (int j = 0; j < 4; j++)
        bRow[j] = (uint32_t)(j * 16 + rB) * 128u;

    const uint32_t vkOff = (uint32_t)(l7 + ((lane >> 3) & 1) * 8) * 128u;
    const uint32_t vdh = ((lane >> 4) & 1) * 16;

#pragma unroll
    for (int i = 0; i < 4; i++) {
        const int idx = tid + i * 256;
        const int row = idx >> 3, ch = idx & 7;
        cp_async16(smc + QOFF + SWZ((uint32_t)(row * 128 + ch * 16)),
                   q + (size_t)(b * NS + qt * 128 + row) * MD + h * HD + ch * 8);
    }

#define ATTN_LOAD(kt, buf)                                                     \
    do {                                                                       \
        _Pragma("unroll")                                                      \
        for (int i = 0; i < 2; i++) {                                          \
            const int idx = tid + i * 256;                                     \
            const int row = idx >> 3, ch = idx & 7;                            \
            const __half* src = kv + (size_t)(b * NS + (kt) * 64 + row) * (2 * MD) \
                              + h * HD + ch * 8;                               \
            const uint32_t off = SWZ((uint32_t)(row * 128 + ch * 16));         \
            cp_async16(smc + KVOFF + (buf) * 16384 + off, src);                \
            cp_async16(smc + KVOFF + (buf) * 16384 + 8192 + off, src + MD);    \
        }                                                                      \
    } while (0)

    ATTN_LOAD(0, 0);
    CP_COMMIT();
    ATTN_LOAD(1, 1);
    CP_COMMIT();

    float O[8][4];
#pragma unroll
    for (int nj = 0; nj < 8; nj++)
#pragma unroll
        for (int e = 0; e < 4; e++) O[nj][e] = 0.0f;
    float m_run[2] = { -INFINITY, -INFINITY };
    float l_run[2] = { 0.0f, 0.0f };

    const int NKT = NS / 64;   // 16
    int buf = 0;
    for (int kt = 0; kt < NKT; kt++) {
        if (kt < NKT - 1) { CP_WAIT(1); } else { CP_WAIT(0); }
        __syncthreads();
        if (kt + 2 < NKT) {
            int nb = buf + 2; if (nb >= 3) nb -= 3;
            ATTN_LOAD(kt + 2, nb);
            CP_COMMIT();
        }

        const uint32_t Kb = sb + KVOFF + buf * 16384;
        const uint32_t Vb = Kb + 8192;

        float sacc[8][4];
#pragma unroll
        for (int nj = 0; nj < 8; nj++)
#pragma unroll
            for (int e = 0; e < 4; e++) sacc[nj][e] = 0.0f;

#pragma unroll
        for (int s = 0; s < 4; s++) {
            const uint32_t so = (uint32_t)s * 32u;
            uint32_t a[4], kb[4][4];
            ldsm4(a, sb + QOFF + aRowOff + ((so + kA) ^ xorv));
#pragma unroll
            for (int j = 0; j < 4; j++)
                ldsm4(kb[j], Kb + bRow[j] + ((so + kB) ^ xorv));
#pragma unroll
            for (int j = 0; j < 4; j++) {
                mma16(sacc[2 * j],     a, kb[j][0], kb[j][1]);
                mma16(sacc[2 * j + 1], a, kb[j][2], kb[j][3]);
            }
        }

#pragma unroll
        for (int nj = 0; nj < 8; nj++)
#pragma unroll
            for (int e = 0; e < 4; e++) sacc[nj][e] *= scale;

#pragma unroll
        for (int r = 0; r < 2; r++) {
            float mx = -INFINITY;
#pragma unroll
            for (int nj = 0; nj < 8; nj++)
                mx = fmaxf(mx, fmaxf(sacc[nj][2 * r], sacc[nj][2 * r + 1]));
            mx = fmaxf(mx, __shfl_xor_sync(0xffffffffu, mx, 1));
            mx = fmaxf(mx, __shfl_xor_sync(0xffffffffu, mx, 2));

            const float m_new = fmaxf(m_run[r], mx);
            const float al = __expf(m_run[r] - m_new);
            float sum = 0.0f;
#pragma unroll
            for (int nj = 0; nj < 8; nj++) {
                const float p0 = __expf(sacc[nj][2 * r] - m_new);
                const float p1 = __expf(sacc[nj][2 * r + 1] - m_new);
                sacc[nj][2 * r] = p0; sacc[nj][2 * r + 1] = p1;
                sum += p0 + p1;
            }
            sum += __shfl_xor_sync(0xffffffffu, sum, 1);
            sum += __shfl_xor_sync(0xffffffffu, sum, 2);

            l_run[r] = l_run[r] * al + sum;
            m_run[r] = m_new;
#pragma unroll
            for (int nj = 0; nj < 8; nj++) {
                O[nj][2 * r] *= al;
                O[nj][2 * r + 1] *= al;
            }
            const int prow = w * 16 + (lane >> 2) + r * 8;
#pragma unroll
            for (int nj = 0; nj < 8; nj++) {
                __half2 pv = __floats2half2_rn(sacc[nj][2 * r], sacc[nj][2 * r + 1]);
                *(uint32_t*)(smc + POFF +
                    SWZ((uint32_t)(prow * 128 + nj * 16 + (lane & 3) * 4))) =
                    *(uint32_t*)&pv;
            }
        }
        __syncwarp();

#pragma unroll
        for (int s = 0; s < 4; s++) {
            const uint32_t so = (uint32_t)s * 32u;
            uint32_t a[4];
            ldsm4(a, sb + POFF + aRowOff + ((so + kA) ^ xorv));
#pragma unroll
            for (int jb = 0; jb < 4; jb++) {
                uint32_t bb[4];
                ldsm4t(bb, Vb + s * 2048 + vkOff + ((jb * 32 + vdh) ^ xorv));
                mma16(O[2 * jb],     a, bb[0], bb[1]);
                mma16(O[2 * jb + 1], a, bb[2], bb[3]);
            }
        }
        if (++buf == 3) buf = 0;
    }
#undef ATTN_LOAD

#pragma unroll
    for (int r = 0; r < 2; r++) {
        const float inv = 1.0f / l_run[r];
        const size_t row = (size_t)(b * NS + qt * 128 + w * 16 + (lane >> 2) + r * 8);
#pragma unroll
        for (int nj = 0; nj < 8; nj++) {
            const int col = h * HD + nj * 8 + (lane & 3) * 2;
            __half2 o = __floats2half2_rn(O[nj][2 * r] * inv, O[nj][2 * r + 1] * inv);
            *(__half2*)(heads + row * MD + col) = o;
        }
    }
}

// ---------------------------------------------------------------------------
extern "C" void kernel_launch(void* const* d_in, const int* in_sizes, int n_in,
                              void* d_out, int out_size)
{
    (void)in_sizes; (void)n_in; (void)out_size;
    const float* query = (const float*)d_in[0];
    const float* value = (const float*)d_in[1];
    const float* Wq    = (const float*)d_in[2];
    const float* bq    = (const float*)d_in[3];
    const float* Wkv   = (const float*)d_in[4];
    const float* bkv   = (const float*)d_in[5];
    const float* Wo    = (const float*)d_in[6];
    const float* bo    = (const float*)d_in[7];
    float* out = (float*)d_out;

    __half *xq, *xv, *q16, *kv16, *h16, *wt16;
    cudaGetSymbolAddress((void**)&xq,   g_xq);
    cudaGetSymbolAddress((void**)&xv,   g_xv);
    cudaGetSymbolAddress((void**)&q16,  g_q16);
    cudaGetSymbolAddress((void**)&kv16, g_kv16);
    cudaGetSymbolAddress((void**)&h16,  g_h16);
    cudaGetSymbolAddress((void**)&wt16, g_wt16);

    cudaFuncSetAttribute(attn_h,
                         cudaFuncAttributeMaxDynamicSharedMemorySize, ATTN_SMEM);
    cudaFuncSetAttribute(gemm_proj,
                         cudaFuncAttributeMaxDynamicSharedMemorySize, GEMM_SMEM);
    cudaFuncSetAttribute(gemm_out,
                         cudaFuncAttributeMaxDynamicSharedMemorySize, GEMM_SMEM);

    const dim3 tblk(32, 8);
    const int n4 = MROWS * MD / 4;

    // ---- all prep upfront (inputs-only dependencies) ----
    f2h_both<<<2048, 256>>>(query, xq, value, xv, n4);
    transpose_h<<<dim3(MD / 32, MD / 32), tblk>>>(Wq, wt16, MD, MD);
    transpose_h<<<dim3(2 * MD / 32, MD / 32), tblk>>>(Wkv, wt16 + MD * MD, MD, 2 * MD);
    transpose_h<<<dim3(MD / 32, MD / 32), tblk>>>(Wo, wt16 + 3 * MD * MD, MD, MD);

    // ---- merged q + kv projection (one launch, 1536 CTAs) ----
    gemm_proj<<<dim3(24, MROWS / 128), 256, GEMM_SMEM>>>(
        xq, xv, wt16, bq, bkv, q16, kv16);

    // ---- fused fp16 tensor-core attention ----
    attn_h<<<dim3(NS / 128, NH, NB), 256, ATTN_SMEM>>>(q16, kv16, h16);

    // ---- out = heads @ Wo + bo (fp32 out) ----
    gemm_out<<<dim3(MD / 128, MROWS / 128), 256, GEMM_SMEM>>>(
        h16, wt16 + 3 * MD * MD, bo, out);
}